// round 17
// baseline (speedup 1.0000x reference)
#include <cuda_runtime.h>

#define NFRAME 320
#define HOP    160
#define LAG    33
#define NTAU_OUT 224          // 257 - 33
#define FN     1000
#define SLEN   160000
#define EXT_LEN 576           // N + TAU - 1
#define EPS    1e-5f

#define WARPS_PER_BLK 4

typedef unsigned long long u64;

__device__ __forceinline__ u64 pk(float a, float b) {
    u64 r; asm("mov.b64 %0, {%1, %2};" : "=l"(r) : "f"(a), "f"(b)); return r;
}
__device__ __forceinline__ void fma2(u64& d, u64 a, u64 b) {
    asm("fma.rn.f32x2 %0, %1, %2, %0;" : "+l"(d) : "l"(a), "l"(b));
}
__device__ __forceinline__ float hadd2(u64 v) {
    float lo, hi;
    asm("mov.b64 {%0, %1}, %2;" : "=f"(lo), "=f"(hi) : "l"(v));
    return lo + hi;
}

// One WARP per (b, f). Lane computes 7 lags tau = 33 + 7*lane + k.
// f32x2 pairwise accumulation. Windows: aligned LDS.64 (E0/E1 parity trick).
// Multipliers: lane-distributed register + __shfl_sync broadcast — NO smem
// broadcast traffic in the hot loop.
__global__ __launch_bounds__(32 * WARPS_PER_BLK)
void xcorr_kernel(const float* __restrict__ x, float* __restrict__ out)
{
    const int w    = threadIdx.x >> 5;
    const int lane = threadIdx.x & 31;
    const int bf   = blockIdx.x * WARPS_PER_BLK + w;
    const int b    = bf / FN;
    const int f    = bf % FN;
    const float* __restrict__ xb = x + (size_t)b * SLEN;

    __shared__ __align__(16) float sE0[WARPS_PER_BLK][EXT_LEN + 8];   // 584 f/row (8B-div)
    __shared__ __align__(16) float sE1[WARPS_PER_BLK][EXT_LEN + 12];  // 588 f/row (8B-div)
    __shared__ float sCs[WARPS_PER_BLK][EXT_LEN + 1];

    float* E0 = sE0[w];
    float* E1 = sE1[w];   // E1[j] = ext[j+1]
    float* cs = sCs[w];

    // ---- Load ext[576]: frame f (320) ++ first 256 of frame f+1 (wrap @ f=999) ----
    #pragma unroll
    for (int r = 0; r < 18; r++) {
        int j = lane + 32 * r;
        int idx;
        if (j < NFRAME)        idx = HOP * f + j;
        else if (f == FN - 1)  idx = j - NFRAME;           // wrap to frame 0
        else                   idx = HOP * f + j - HOP;    // frame f+1
        float v = (idx < SLEN) ? xb[idx] : 0.0f;           // zero-pad tail
        E0[j] = v;
        if (j > 0) E1[j - 1] = v;                          // shifted copy
    }
    if (lane < 8)  E0[EXT_LEN + lane] = 0.0f;              // E0[576..583] = 0
    if (lane < 13) E1[EXT_LEN - 1 + lane] = 0.0f;          // E1[575..587] = 0
    __syncwarp();

    // ---- Prefix sum of squares (per-warp): lane owns ext[18L .. 18L+17] ----
    {
        float loc[18];
        float s = 0.0f;
        #pragma unroll
        for (int i = 0; i < 18; i++) {
            float v = E0[18 * lane + i];
            s += v * v;
            loc[i] = s;
        }
        float v = s;
        #pragma unroll
        for (int d = 1; d < 32; d <<= 1) {
            float n = __shfl_up_sync(0xffffffffu, v, d);
            if (lane >= d) v += n;
        }
        float excl = v - s;
        if (lane == 0) cs[0] = 0.0f;
        #pragma unroll
        for (int i = 0; i < 18; i++)
            cs[18 * lane + 1 + i] = excl + loc[i];
    }
    __syncwarp();

    // ---- Main loop ----
    const int tau0 = LAG + 7 * lane;
    // wpair[i] = (ext[tau0+2i], ext[tau0+2i+1]) — 8B-aligned LDS.64
    const u64* wpair = (tau0 & 1) ? (const u64*)(E1 + (tau0 - 1))
                                  : (const u64*)(E0 + tau0);

    u64 d0 = wpair[0], d1 = wpair[1], d2 = wpair[2], d3 = wpair[3];
    const float c1 = E0[tau0 + 1], c3 = E0[tau0 + 3], c5 = E0[tau0 + 5];
    const float f0 = E0[0];

    u64 a0 = 0, a1 = 0, a2 = 0, a3 = 0, a4 = 0, a5 = 0, a6 = 0;

    // 10 blocks of 32 samples; 4 groups of 8 samples per block.
    for (int c = 0; c < 10; c++) {
        const float mcur  = E0[32 * c + lane];                  // lane-distinct, 1 wf
        const float mlast = (c < 9) ? E0[32 * c + 32] : 0.0f;   // fr[32c+32] (fr[320]:=0)

        #pragma unroll
        for (int u = 0; u < 4; u++) {
            const int h = 16 * c + 4 * u;      // global pair index base (= 4g)
            const int s = 8 * u;               // scalar base within block

            float s0 = __shfl_sync(0xffffffffu, mcur, s + 0);
            float s1 = __shfl_sync(0xffffffffu, mcur, s + 1);
            float s2 = __shfl_sync(0xffffffffu, mcur, s + 2);
            float s3 = __shfl_sync(0xffffffffu, mcur, s + 3);
            float s4 = __shfl_sync(0xffffffffu, mcur, s + 4);
            float s5 = __shfl_sync(0xffffffffu, mcur, s + 5);
            float s6 = __shfl_sync(0xffffffffu, mcur, s + 6);
            float s7 = __shfl_sync(0xffffffffu, mcur, s + 7);
            float s8 = (u < 3) ? __shfl_sync(0xffffffffu, mcur, s + 8) : mlast;

            u64 mab0 = pk(s0, s1), mab1 = pk(s2, s3), mab2 = pk(s4, s5), mab3 = pk(s6, s7);
            u64 mbc0 = pk(s1, s2), mbc1 = pk(s3, s4), mbc2 = pk(s5, s6), mbc3 = pk(s7, s8);

            // samples (8g, 8g+1)
            fma2(a0, mab0, d0); fma2(a2, mab0, d1); fma2(a4, mab0, d2); fma2(a6, mab0, d3);
            fma2(a1, mbc0, d1); fma2(a3, mbc0, d2); fma2(a5, mbc0, d3);
            u64 d4 = wpair[h + 4];
            // samples (8g+2, 8g+3)
            fma2(a0, mab1, d1); fma2(a2, mab1, d2); fma2(a4, mab1, d3); fma2(a6, mab1, d4);
            fma2(a1, mbc1, d2); fma2(a3, mbc1, d3); fma2(a5, mbc1, d4);
            u64 d5 = wpair[h + 5];
            // samples (8g+4, 8g+5)
            fma2(a0, mab2, d2); fma2(a2, mab2, d3); fma2(a4, mab2, d4); fma2(a6, mab2, d5);
            fma2(a1, mbc2, d3); fma2(a3, mbc2, d4); fma2(a5, mbc2, d5);
            u64 d6 = wpair[h + 6];
            // samples (8g+6, 8g+7)
            fma2(a0, mab3, d3); fma2(a2, mab3, d4); fma2(a4, mab3, d5); fma2(a6, mab3, d6);
            fma2(a1, mbc3, d4); fma2(a3, mbc3, d5); fma2(a5, mbc3, d6);
            u64 d7 = wpair[h + 7];   // last group reads padded zeros region — safe

            d0 = d4; d1 = d5; d2 = d6; d3 = d7;
        }
    }

    // ---- Horizontal add + odd-k n=0 correction ----
    float r0 = hadd2(a0);
    float r1 = hadd2(a1) + f0 * c1;
    float r2 = hadd2(a2);
    float r3 = hadd2(a3) + f0 * c3;
    float r4 = hadd2(a4);
    float r5 = hadd2(a5) + f0 * c5;
    float r6 = hadd2(a6);

    // ---- Normalize and store ----
    const float e0 = cs[NFRAME];
    float* __restrict__ o = out + (size_t)bf * NTAU_OUT + 7 * lane;
    float acc[7] = {r0, r1, r2, r3, r4, r5, r6};
    #pragma unroll
    for (int k = 0; k < 7; k++) {
        float etau = cs[tau0 + k + NFRAME] - cs[tau0 + k];
        o[k] = 2.0f * acc[k] / (e0 + etau + EPS);
    }
}

extern "C" void kernel_launch(void* const* d_in, const int* in_sizes, int n_in,
                              void* d_out, int out_size)
{
    const float* x = (const float*)d_in[0];
    float* out = (float*)d_out;
    (void)in_sizes; (void)n_in; (void)out_size;
    xcorr_kernel<<<32 * FN / WARPS_PER_BLK, 32 * WARPS_PER_BLK>>>(x, out);
}